// round 6
// baseline (speedup 1.0000x reference)
#include <cuda_runtime.h>
#include <math.h>

// Problem constants (B=128, N=511, M=256, R=64, IN=512)
#define BATCH  128
#define NNODES 511
#define MDIM   256
#define RDIM   64
#define INDIM  512

// GEMM tiling: block tile 64 rows x 64 cols; thread tile 8 rows x 2 cols x NACC
#define BM 64
#define BN 64
#define BK 16
#define SAS 68      // sA row stride (words); 68*4B = 272 mult of 16 -> aligned LDS.128
#define NTH 256

typedef unsigned long long ull;

// Persistent scratch (device globals; no allocation)
__device__ float g_h_buf[(size_t)NNODES * BATCH * MDIM];   // [node][b][m]
__device__ float g_c_buf[(size_t)NNODES * BATCH * MDIM];
__device__ float g_h1[(size_t)128 * BATCH * MDIM];         // cell1 h
__device__ float g_c1[(size_t)128 * BATCH * MDIM];         // cell1 c
__device__ float g_ht[(size_t)128 * BATCH * MDIM];         // h_tilde

__device__ __forceinline__ float sigf(float x) { return 1.0f / (1.0f + expf(-x)); }

// ---- packed f32x2 helpers (sm_103a FFMA2) ----
__device__ __forceinline__ ull pack2(float x) {
    ull r;
    unsigned u = __float_as_uint(x);
    asm("mov.b64 %0, {%1, %1};" : "=l"(r) : "r"(u));
    return r;
}
__device__ __forceinline__ void ffma2(ull& d, ull a, ull b) {
    asm("fma.rn.f32x2 %0, %1, %2, %0;" : "+l"(d) : "l"(a), "l"(b));
}
__device__ __forceinline__ void unp2(ull v, float& lo, float& hi) {
    unsigned l, h;
    asm("mov.b64 {%0, %1}, %2;" : "=r"(l), "=r"(h) : "l"(v));
    lo = __uint_as_float(l);
    hi = __uint_as_float(h);
}

// 8-row x 2-col x NACC tiled GEMM phase. Double-buffered smem, 1 sync/step,
// register prefetch. acc[j][r] = packed (col m0, col m0+1) for row r.
// Warp layout: ty = tid>>5 (row group of 8), tx = tid&31 (col pair).
template<int NACC>
__device__ __forceinline__ void gemm82(
    ull (*acc)[8],
    const float* const* rowptr,
    const float* const (&Bp)[NACC],
    int ldb, int K,
    float* sA, float* sB, int tid)
{
    const int ty = tid >> 5, tx = tid & 31;
    const int ar = tid >> 2, akv = (tid & 3) * 4;
    const int bk = tid >> 4, bnv = (tid & 15) * 4;
    const float* aptr = rowptr[ar];
    const int ASZ = BK * SAS;
    const int BSZ = NACC * BK * BN;

    float4 av = *reinterpret_cast<const float4*>(aptr + akv);
    float4 bv[NACC];
#pragma unroll
    for (int j = 0; j < NACC; j++)
        bv[j] = *reinterpret_cast<const float4*>(Bp[j] + (size_t)bk * ldb + bnv);

    sA[(akv + 0) * SAS + ar] = av.x;
    sA[(akv + 1) * SAS + ar] = av.y;
    sA[(akv + 2) * SAS + ar] = av.z;
    sA[(akv + 3) * SAS + ar] = av.w;
#pragma unroll
    for (int j = 0; j < NACC; j++)
        *reinterpret_cast<float4*>(&sB[(j * BK + bk) * BN + bnv]) = bv[j];
    __syncthreads();

    int cur = 0;
    for (int k0 = 0; k0 < K; k0 += BK) {
        const bool more = (k0 + BK) < K;
        if (more) {
            av = *reinterpret_cast<const float4*>(aptr + k0 + BK + akv);
#pragma unroll
            for (int j = 0; j < NACC; j++)
                bv[j] = *reinterpret_cast<const float4*>(Bp[j] + (size_t)(k0 + BK + bk) * ldb + bnv);
        }
        const float* cA = sA + cur * ASZ;
        const float* cB = sB + cur * BSZ;
#pragma unroll
        for (int kk = 0; kk < BK; kk++) {
            float4 alo = *reinterpret_cast<const float4*>(cA + kk * SAS + ty * 8);
            float4 ahi = *reinterpret_cast<const float4*>(cA + kk * SAS + ty * 8 + 4);
            ull a[8];
            a[0] = pack2(alo.x); a[1] = pack2(alo.y); a[2] = pack2(alo.z); a[3] = pack2(alo.w);
            a[4] = pack2(ahi.x); a[5] = pack2(ahi.y); a[6] = pack2(ahi.z); a[7] = pack2(ahi.w);
#pragma unroll
            for (int j = 0; j < NACC; j++) {
                ull b = *reinterpret_cast<const ull*>(cB + (j * BK + kk) * BN + tx * 2);
#pragma unroll
                for (int r = 0; r < 8; r++)
                    ffma2(acc[j][r], a[r], b);
            }
        }
        if (more) {
            const int nxt = cur ^ 1;
            float* nA = sA + nxt * ASZ;
            float* nB = sB + nxt * BSZ;
            nA[(akv + 0) * SAS + ar] = av.x;
            nA[(akv + 1) * SAS + ar] = av.y;
            nA[(akv + 2) * SAS + ar] = av.z;
            nA[(akv + 3) * SAS + ar] = av.w;
#pragma unroll
            for (int j = 0; j < NACC; j++)
                *reinterpret_cast<float4*>(&nB[(j * BK + bk) * BN + bnv]) = bv[j];
            __syncthreads();
            cur = nxt;
        }
    }
}

// Dual-A variant: two A sources sharing one B tile. acc0 <- A0*B, acc1 <- A1*B.
__device__ __forceinline__ void gemm82_dual(
    ull* acc0, ull* acc1,
    const float* const* rp0, const float* const* rp1,
    const float* Bp, int ldb, int K,
    float* sA0, float* sA1, float* sB, int tid)
{
    const int ty = tid >> 5, tx = tid & 31;
    const int ar = tid >> 2, akv = (tid & 3) * 4;
    const int bk = tid >> 4, bnv = (tid & 15) * 4;
    const float* ap0 = rp0[ar];
    const float* ap1 = rp1[ar];
    const int ASZ = BK * SAS;
    const int BSZ = BK * BN;

    float4 a0v = *reinterpret_cast<const float4*>(ap0 + akv);
    float4 a1v = *reinterpret_cast<const float4*>(ap1 + akv);
    float4 bv = *reinterpret_cast<const float4*>(Bp + (size_t)bk * ldb + bnv);

#pragma unroll
    for (int j = 0; j < 4; j++) {
        sA0[(akv + j) * SAS + ar] = (&a0v.x)[j];
        sA1[(akv + j) * SAS + ar] = (&a1v.x)[j];
    }
    *reinterpret_cast<float4*>(&sB[bk * BN + bnv]) = bv;
    __syncthreads();

    int cur = 0;
    for (int k0 = 0; k0 < K; k0 += BK) {
        const bool more = (k0 + BK) < K;
        if (more) {
            a0v = *reinterpret_cast<const float4*>(ap0 + k0 + BK + akv);
            a1v = *reinterpret_cast<const float4*>(ap1 + k0 + BK + akv);
            bv  = *reinterpret_cast<const float4*>(Bp + (size_t)(k0 + BK + bk) * ldb + bnv);
        }
        const float* cA0 = sA0 + cur * ASZ;
        const float* cA1 = sA1 + cur * ASZ;
        const float* cB = sB + cur * BSZ;
#pragma unroll
        for (int kk = 0; kk < BK; kk++) {
            float4 l0 = *reinterpret_cast<const float4*>(cA0 + kk * SAS + ty * 8);
            float4 h0 = *reinterpret_cast<const float4*>(cA0 + kk * SAS + ty * 8 + 4);
            float4 l1 = *reinterpret_cast<const float4*>(cA1 + kk * SAS + ty * 8);
            float4 h1 = *reinterpret_cast<const float4*>(cA1 + kk * SAS + ty * 8 + 4);
            ull b = *reinterpret_cast<const ull*>(cB + kk * BN + tx * 2);
#pragma unroll
            for (int r = 0; r < 4; r++) {
                ffma2(acc0[r],     pack2((&l0.x)[r]), b);
                ffma2(acc0[4 + r], pack2((&h0.x)[r]), b);
                ffma2(acc1[r],     pack2((&l1.x)[r]), b);
                ffma2(acc1[4 + r], pack2((&h1.x)[r]), b);
            }
        }
        if (more) {
            const int nxt = cur ^ 1;
            float* nA0 = sA0 + nxt * ASZ;
            float* nA1 = sA1 + nxt * ASZ;
            float* nB = sB + nxt * BSZ;
#pragma unroll
            for (int j = 0; j < 4; j++) {
                nA0[(akv + j) * SAS + ar] = (&a0v.x)[j];
                nA1[(akv + j) * SAS + ar] = (&a1v.x)[j];
            }
            *reinterpret_cast<float4*>(&nB[bk * BN + bnv]) = bv;
            __syncthreads();
            cur = nxt;
        }
    }
}

// ---------------- Leaf kernel: nodes 255..510 ----------------
__global__ void __launch_bounds__(NTH, 2)
k_leaf(const float* __restrict__ wte,
       const float* __restrict__ Wix, const float* __restrict__ Wux, const float* __restrict__ Wox,
       const float* __restrict__ bix, const float* __restrict__ bux, const float* __restrict__ boxb,
       const float* __restrict__ bih, const float* __restrict__ buh, const float* __restrict__ boh)
{
    __shared__ __align__(16) float sA[2 * BK * SAS];
    __shared__ __align__(16) float sB[2 * 3 * BK * BN];
    __shared__ const float* rowptr[BM];
    const int tid = threadIdx.x;
    const int rb = blockIdx.x * BM;
    const int n0 = blockIdx.y * BN;

    ull acc[3][8];
#pragma unroll
    for (int j = 0; j < 3; j++)
#pragma unroll
        for (int r = 0; r < 8; r++) acc[j][r] = 0ull;

    if (tid < BM) {
        int r = rb + tid;
        int node = 255 + (r >> 7);
        int b = r & 127;
        rowptr[tid] = wte + (size_t)(b * NNODES + node) * INDIM;
    }
    __syncthreads();
    {
        const float* const Bp[3] = { Wix + n0, Wux + n0, Wox + n0 };
        gemm82<3>(acc, rowptr, Bp, MDIM, INDIM, sA, sB, tid);
    }
    const int ty = tid >> 5, tx = tid & 31;
    const int m0 = n0 + tx * 2;
    float bi0 = bix[m0] + bih[m0],     bi1 = bix[m0 + 1] + bih[m0 + 1];
    float bu0 = bux[m0] + buh[m0],     bu1 = bux[m0 + 1] + buh[m0 + 1];
    float bo0 = boxb[m0] + boh[m0],    bo1 = boxb[m0 + 1] + boh[m0 + 1];
#pragma unroll
    for (int r8 = 0; r8 < 8; r8++) {
        int r = rb + ty * 8 + r8;
        int node = 255 + (r >> 7);
        int b = r & 127;
        size_t base = (size_t)(node * BATCH + b) * MDIM + m0;
        float i0, i1, u0, u1, o0, o1;
        unp2(acc[0][r8], i0, i1);
        unp2(acc[1][r8], u0, u1);
        unp2(acc[2][r8], o0, o1);
        float c0 = sigf(i0 + bi0) * tanhf(u0 + bu0);
        float c1 = sigf(i1 + bi1) * tanhf(u1 + bu1);
        float h0 = sigf(o0 + bo0) * tanhf(c0);
        float h1 = sigf(o1 + bo1) * tanhf(c1);
        *reinterpret_cast<float2*>(&g_c_buf[base]) = make_float2(c0, c1);
        *reinterpret_cast<float2*>(&g_h_buf[base]) = make_float2(h0, h1);
    }
}

// ---------------- Cell 1: x = [h(2n+1), rel(2n+1)], h=c=0 (f dead) ----------------
__global__ void __launch_bounds__(NTH, 2)
k_cell1(const float* __restrict__ rel,
        const float* __restrict__ Wsih,
        const float* __restrict__ bsi, const float* __restrict__ bsh,
        int nodeBase)
{
    __shared__ __align__(16) float sA[2 * BK * SAS];
    __shared__ __align__(16) float sB[2 * 3 * BK * BN];
    __shared__ const float* rowptr[BM];
    const int tid = threadIdx.x;
    const int rb = blockIdx.x * BM;
    const int n0 = blockIdx.y * BN;

    ull acc[3][8];  // i, g, o
#pragma unroll
    for (int j = 0; j < 3; j++)
#pragma unroll
        for (int r = 0; r < 8; r++) acc[j][r] = 0ull;

    if (tid < BM) {
        int r = rb + tid;
        int node = nodeBase + (r >> 7);
        int b = r & 127;
        rowptr[tid] = g_h_buf + (size_t)((2 * node + 1) * BATCH + b) * MDIM;
    }
    __syncthreads();
    {
        const float* const Bp[3] = { Wsih + n0, Wsih + 512 + n0, Wsih + 768 + n0 };
        gemm82<3>(acc, rowptr, Bp, 1024, MDIM, sA, sB, tid);
    }
    __syncthreads();
    if (tid < BM) {
        int r = rb + tid;
        int node = nodeBase + (r >> 7);
        int b = r & 127;
        rowptr[tid] = rel + (size_t)(b * NNODES + 2 * node + 1) * RDIM;
    }
    __syncthreads();
    {
        const float* const Bp[3] = { Wsih + 256 * 1024 + n0, Wsih + 256 * 1024 + 512 + n0,
                                     Wsih + 256 * 1024 + 768 + n0 };
        gemm82<3>(acc, rowptr, Bp, 1024, RDIM, sA, sB, tid);
    }
    const int ty = tid >> 5, tx = tid & 31;
    const int m0 = n0 + tx * 2;
    float bi0 = bsi[m0] + bsh[m0],                 bi1 = bsi[m0 + 1] + bsh[m0 + 1];
    float bg0 = bsi[512 + m0] + bsh[512 + m0],     bg1 = bsi[512 + m0 + 1] + bsh[512 + m0 + 1];
    float bo0 = bsi[768 + m0] + bsh[768 + m0],     bo1 = bsi[768 + m0 + 1] + bsh[768 + m0 + 1];
#pragma unroll
    for (int r8 = 0; r8 < 8; r8++) {
        int r = rb + ty * 8 + r8;
        size_t base = (size_t)r * MDIM + m0;
        float i0, i1, g0, g1, o0, o1;
        unp2(acc[0][r8], i0, i1);
        unp2(acc[1][r8], g0, g1);
        unp2(acc[2][r8], o0, o1);
        float c0 = sigf(i0 + bi0) * tanhf(g0 + bg0);
        float c1 = sigf(i1 + bi1) * tanhf(g1 + bg1);
        float h0 = sigf(o0 + bo0) * tanhf(c0);
        float h1 = sigf(o1 + bo1) * tanhf(c1);
        *reinterpret_cast<float2*>(&g_c1[base]) = make_float2(c0, c1);
        *reinterpret_cast<float2*>(&g_h1[base]) = make_float2(h0, h1);
    }
}

// ---------------- Cell 2: x = [h(2n+2), rel(2n+2)], state = cell1 ----------------
__global__ void __launch_bounds__(NTH, 2)
k_cell2(const float* __restrict__ rel,
        const float* __restrict__ Wsih, const float* __restrict__ Wshh,
        const float* __restrict__ bsi, const float* __restrict__ bsh,
        int nodeBase)
{
    __shared__ __align__(16) float sA[2 * BK * SAS];
    __shared__ __align__(16) float sB[2 * 4 * BK * BN];
    __shared__ const float* rowptr[BM];
    const int tid = threadIdx.x;
    const int rb = blockIdx.x * BM;
    const int n0 = blockIdx.y * BN;

    ull acc[4][8];  // i, f, g, o
#pragma unroll
    for (int j = 0; j < 4; j++)
#pragma unroll
        for (int r = 0; r < 8; r++) acc[j][r] = 0ull;

    if (tid < BM) {
        int r = rb + tid;
        int node = nodeBase + (r >> 7);
        int b = r & 127;
        rowptr[tid] = g_h_buf + (size_t)((2 * node + 2) * BATCH + b) * MDIM;
    }
    __syncthreads();
    {
        const float* const Bp[4] = { Wsih + n0, Wsih + 256 + n0, Wsih + 512 + n0, Wsih + 768 + n0 };
        gemm82<4>(acc, rowptr, Bp, 1024, MDIM, sA, sB, tid);
    }
    __syncthreads();
    if (tid < BM) {
        int r = rb + tid;
        int node = nodeBase + (r >> 7);
        int b = r & 127;
        rowptr[tid] = rel + (size_t)(b * NNODES + 2 * node + 2) * RDIM;
    }
    __syncthreads();
    {
        const float* const Bp[4] = { Wsih + 256 * 1024 + n0, Wsih + 256 * 1024 + 256 + n0,
                                     Wsih + 256 * 1024 + 512 + n0, Wsih + 256 * 1024 + 768 + n0 };
        gemm82<4>(acc, rowptr, Bp, 1024, RDIM, sA, sB, tid);
    }
    __syncthreads();
    if (tid < BM) {
        int r = rb + tid;
        rowptr[tid] = g_h1 + (size_t)r * MDIM;
    }
    __syncthreads();
    {
        const float* const Bp[4] = { Wshh + n0, Wshh + 256 + n0, Wshh + 512 + n0, Wshh + 768 + n0 };
        gemm82<4>(acc, rowptr, Bp, 1024, MDIM, sA, sB, tid);
    }
    const int ty = tid >> 5, tx = tid & 31;
    const int m0 = n0 + tx * 2;
    float bi0 = bsi[m0] + bsh[m0],                 bi1 = bsi[m0 + 1] + bsh[m0 + 1];
    float bf0 = bsi[256 + m0] + bsh[256 + m0],     bf1 = bsi[256 + m0 + 1] + bsh[256 + m0 + 1];
    float bg0 = bsi[512 + m0] + bsh[512 + m0],     bg1 = bsi[512 + m0 + 1] + bsh[512 + m0 + 1];
    float bo0 = bsi[768 + m0] + bsh[768 + m0],     bo1 = bsi[768 + m0 + 1] + bsh[768 + m0 + 1];
#pragma unroll
    for (int r8 = 0; r8 < 8; r8++) {
        int r = rb + ty * 8 + r8;
        size_t base = (size_t)r * MDIM + m0;
        float i0, i1, f0, f1, g0, g1, o0, o1;
        unp2(acc[0][r8], i0, i1);
        unp2(acc[1][r8], f0, f1);
        unp2(acc[2][r8], g0, g1);
        unp2(acc[3][r8], o0, o1);
        float2 c1v = *reinterpret_cast<const float2*>(&g_c1[base]);
        float c20 = sigf(f0 + bf0) * c1v.x + sigf(i0 + bi0) * tanhf(g0 + bg0);
        float c21 = sigf(f1 + bf1) * c1v.y + sigf(i1 + bi1) * tanhf(g1 + bg1);
        float h0 = sigf(o0 + bo0) * tanhf(c20);
        float h1 = sigf(o1 + bo1) * tanhf(c21);
        *reinterpret_cast<float2*>(&g_ht[base]) = make_float2(h0, h1);
    }
}

// ---------------- Tree gates: i,u,o,fx + dual f0/f1 -> c, h ----------------
__global__ void __launch_bounds__(NTH, 2)
k_gates(const float* __restrict__ wte,
        const float* __restrict__ Wix, const float* __restrict__ Wux,
        const float* __restrict__ Wox, const float* __restrict__ Wfx,
        const float* __restrict__ Wih, const float* __restrict__ Wuh,
        const float* __restrict__ Woh, const float* __restrict__ Wfh,
        const float* __restrict__ bix, const float* __restrict__ bux,
        const float* __restrict__ boxb, const float* __restrict__ bfx,
        const float* __restrict__ bih, const float* __restrict__ buh,
        const float* __restrict__ boh, const float* __restrict__ bfh,
        int nodeBase, float* __restrict__ outp)
{
    // pool: [0, 2176) = sA | [2176, 10368) = sB(4 gates)  (floats)
    // dual phase: sA0 = pool, sB_dual = pool+2176 (2048 f), sA1 = pool+2176+2048
    __shared__ __align__(16) float sPool[2 * BK * SAS + 2 * 4 * BK * BN];
    __shared__ const float* rowptr[BM];
    __shared__ const float* rp1[BM];
    float* sA = sPool;
    float* sB = sPool + 2 * BK * SAS;
    const int tid = threadIdx.x;
    const int rb = blockIdx.x * BM;
    const int n0 = blockIdx.y * BN;

    ull acc[4][8];   // i, u, o, fx
    ull accF0[8], accF1[8];
#pragma unroll
    for (int j = 0; j < 4; j++)
#pragma unroll
        for (int r = 0; r < 8; r++) acc[j][r] = 0ull;
#pragma unroll
    for (int r = 0; r < 8; r++) { accF0[r] = 0ull; accF1[r] = 0ull; }

    // phase 1: x part (K = 512), all 4 gates
    if (tid < BM) {
        int r = rb + tid;
        int node = nodeBase + (r >> 7);
        int b = r & 127;
        rowptr[tid] = wte + (size_t)(b * NNODES + node) * INDIM;
    }
    __syncthreads();
    {
        const float* const Bp[4] = { Wix + n0, Wux + n0, Wox + n0, Wfx + n0 };
        gemm82<4>(acc, rowptr, Bp, MDIM, INDIM, sA, sB, tid);
    }
    // phase 2: h_tilde part for i,u,o (K = 256)
    __syncthreads();
    if (tid < BM) {
        int r = rb + tid;
        rowptr[tid] = g_ht + (size_t)r * MDIM;
    }
    __syncthreads();
    {
        const float* const Bp[3] = { Wih + n0, Wuh + n0, Woh + n0 };
        gemm82<3>(acc, rowptr, Bp, MDIM, MDIM, sA, sB, tid);
    }
    // phase 3: dual f0/f1 = h(2n+1/2n+2) @ Wfh (shared B tile)
    __syncthreads();
    if (tid < BM) {
        int r = rb + tid;
        int node = nodeBase + (r >> 7);
        int b = r & 127;
        rowptr[tid] = g_h_buf + (size_t)((2 * node + 1) * BATCH + b) * MDIM;
        rp1[tid]    = g_h_buf + (size_t)((2 * node + 2) * BATCH + b) * MDIM;
    }
    __syncthreads();
    {
        float* sBd  = sPool + 2 * BK * SAS;
        float* sA1p = sPool + 2 * BK * SAS + 2 * BK * BN;
        gemm82_dual(accF0, accF1, rowptr, rp1, Wfh + n0, MDIM, MDIM, sA, sA1p, sBd, tid);
    }

    const int ty = tid >> 5, tx = tid & 31;
    const int m0 = n0 + tx * 2;
    float bi0 = bix[m0] + bih[m0],    bi1 = bix[m0 + 1] + bih[m0 + 1];
    float bu0 = bux[m0] + buh[m0],    bu1 = bux[m0 + 1] + buh[m0 + 1];
    float bo0 = boxb[m0] + boh[m0],   bo1 = boxb[m0 + 1] + boh[m0 + 1];
    float bf0 = bfx[m0] + bfh[m0],    bf1 = bfx[m0 + 1] + bfh[m0 + 1];
#pragma unroll
    for (int r8 = 0; r8 < 8; r8++) {
        int r = rb + ty * 8 + r8;
        int node = nodeBase + (r >> 7);
        int b = r & 127;
        size_t base  = (size_t)(node * BATCH + b) * MDIM + m0;
        size_t base0 = (size_t)((2 * node + 1) * BATCH + b) * MDIM + m0;
        size_t base1 = (size_t)((2 * node + 2) * BATCH + b) * MDIM + m0;
        float i0, i1, u0, u1, o0, o1, fx0, fx1, d00, d01, d10, d11;
        unp2(acc[0][r8], i0, i1);
        unp2(acc[1][r8], u0, u1);
        unp2(acc[2][r8], o0, o1);
        unp2(acc[3][r8], fx0, fx1);
        unp2(accF0[r8], d00, d01);
        unp2(accF1[r8], d10, d11);
        float2 cc0 = *reinterpret_cast<const float2*>(&g_c_buf[base0]);
        float2 cc1 = *reinterpret_cast<const float2*>(&g_c_buf[base1]);
        float c0 = sigf(i0 + bi0) * tanhf(u0 + bu0)
                 + sigf(fx0 + bf0 + d00) * cc0.x + sigf(fx0 + bf0 + d10) * cc1.x;
        float c1 = sigf(i1 + bi1) * tanhf(u1 + bu1)
                 + sigf(fx1 + bf1 + d01) * cc0.y + sigf(fx1 + bf1 + d11) * cc1.y;
        float h0 = sigf(o0 + bo0) * tanhf(c0);
        float h1 = sigf(o1 + bo1) * tanhf(c1);
        *reinterpret_cast<float2*>(&g_c_buf[base]) = make_float2(c0, c1);
        *reinterpret_cast<float2*>(&g_h_buf[base]) = make_float2(h0, h1);
        if (outp)
            *reinterpret_cast<float2*>(&outp[(size_t)r * MDIM + m0]) = make_float2(h0, h1);
    }
}

extern "C" void kernel_launch(void* const* d_in, const int* in_sizes, int n_in,
                              void* d_out, int out_size)
{
    const float* wte = nullptr;
    const float* rel = nullptr;
    const float* Wx[4];  int nWx = 0;   // ix, fx, ux, ox
    const float* Wh[4];  int nWh = 0;   // ih, fh, uh, oh
    const float* b256[8]; int nb = 0;   // bix,bfx,bux,box,bih,bfh,buh,boh
    const float* Wsih = nullptr;
    const float* Wshh = nullptr;
    const float* bseq[2]; int nbs = 0;  // b_seq_ih, b_seq_hh

    for (int i = 0; i < n_in; i++) {
        int s = in_sizes[i];
        const float* p = (const float*)d_in[i];
        switch (s) {
            case 33488896: wte = p; break;                 // 128*511*512
            case 4186112:  rel = p; break;                 // 128*511*64
            case 131072:   if (nWx < 4) Wx[nWx++] = p; break;   // 512*256
            case 65536:    if (nWh < 4) Wh[nWh++] = p; break;   // 256*256
            case 256:      if (nb < 8) b256[nb++] = p; break;
            case 327680:   Wsih = p; break;                // 320*1024
            case 262144:   Wshh = p; break;                // 256*1024
            case 1024:     if (nbs < 2) bseq[nbs++] = p; break;
            default: break;  // n_nodes (size 1): compile-time constant
        }
    }
    const float *Wix = Wx[0], *Wfx = Wx[1], *Wux = Wx[2], *Wox = Wx[3];
    const float *Wih = Wh[0], *Wfh = Wh[1], *Wuh = Wh[2], *Woh = Wh[3];
    const float *bix = b256[0], *bfx = b256[1], *bux = b256[2], *boxb = b256[3];
    const float *bih = b256[4], *bfh = b256[5], *buh = b256[6], *boh = b256[7];
    float* out = (float*)d_out;

    dim3 blk(NTH);

    // Level 8: all 256 leaves at once (32768 rows)
    k_leaf<<<dim3(512, 4), blk>>>(wte, Wix, Wux, Wox, bix, bux, boxb, bih, buh, boh);

    // Levels 7..0 (internal nodes)
    for (int L = 7; L >= 0; --L) {
        int P = 1 << L;
        int nodeBase = P - 1;
        int rowBlocks = (P * BATCH) / BM;
        dim3 grd(rowBlocks, 4);
        k_cell1<<<grd, blk>>>(rel, Wsih, bseq[0], bseq[1], nodeBase);
        k_cell2<<<grd, blk>>>(rel, Wsih, Wshh, bseq[0], bseq[1], nodeBase);
        k_gates<<<grd, blk>>>(wte, Wix, Wux, Wox, Wfx, Wih, Wuh, Woh, Wfh,
                              bix, bux, boxb, bfx, bih, buh, boh, bfh,
                              nodeBase, (L == 0) ? out : nullptr);
    }
}

// round 9
// speedup vs baseline: 1.5416x; 1.5416x over previous
#include <cuda_runtime.h>
#include <cuda_bf16.h>
#include <cstdint>
#include <cstddef>
#include <math.h>

// Problem constants (B=128, N=511, M=256, R=64, IN=512)
#define BATCH  128
#define NNODES 511
#define MDIM   256
#define RDIM   64
#define INDIM  512

// FFMA GEMM tiling (R3 config)
#define BM 64
#define BN 64
#define BK 16
#define SAS 66
#define NTH 256

typedef unsigned long long ull;

// Persistent scratch (device globals; no allocation)
__device__ float g_h_buf[(size_t)NNODES * BATCH * MDIM];
__device__ float g_c_buf[(size_t)NNODES * BATCH * MDIM];
__device__ float g_h1[(size_t)128 * BATCH * MDIM];
__device__ float g_c1[(size_t)128 * BATCH * MDIM];
__device__ float g_ht[(size_t)128 * BATCH * MDIM];

// bf16 leaf path scratch
__device__ __nv_bfloat16 g_wte_hi[(size_t)BATCH * NNODES * INDIM];
__device__ __nv_bfloat16 g_wte_lo[(size_t)BATCH * NNODES * INDIM];
__device__ __nv_bfloat16 g_wt_hi[3 * 256 * 512];   // [gate][n][k] == [768][512]
__device__ __nv_bfloat16 g_wt_lo[3 * 256 * 512];
__device__ float g_pre[(size_t)3 * 32768 * 256];   // leaf pre-activations [gate][row][m]

__device__ __forceinline__ float sigf(float x) { return 1.0f / (1.0f + expf(-x)); }

// ---- packed f32x2 helpers (sm_103a FFMA2) ----
__device__ __forceinline__ ull pack2(float x) {
    ull r;
    unsigned u = __float_as_uint(x);
    asm("mov.b64 %0, {%1, %1};" : "=l"(r) : "r"(u));
    return r;
}
__device__ __forceinline__ void ffma2(ull& d, ull a, ull b) {
    asm("fma.rn.f32x2 %0, %1, %2, %0;" : "+l"(d) : "l"(a), "l"(b));
}
__device__ __forceinline__ void unp2(ull v, float& lo, float& hi) {
    unsigned l, h;
    asm("mov.b64 {%0, %1}, %2;" : "=r"(l), "=r"(h) : "l"(v));
    lo = __uint_as_float(l);
    hi = __uint_as_float(h);
}

// ---- mma.sync helpers (baseline PTX; works on sm_103 target) ----
__device__ __forceinline__ uint32_t smem_u32(const void* p) {
    uint32_t a;
    asm("{ .reg .u64 t; cvta.to.shared.u64 t, %1; cvt.u32.u64 %0, t; }" : "=r"(a) : "l"(p));
    return a;
}
__device__ __forceinline__ void ldm4(uint32_t* r, uint32_t addr) {
    asm volatile("ldmatrix.sync.aligned.m8n8.x4.shared.b16 {%0,%1,%2,%3}, [%4];"
        : "=r"(r[0]), "=r"(r[1]), "=r"(r[2]), "=r"(r[3]) : "r"(addr));
}
__device__ __forceinline__ void mma_bf16(float* c, const uint32_t* a,
                                         uint32_t b0, uint32_t b1) {
    asm volatile(
        "mma.sync.aligned.m16n8k16.row.col.f32.bf16.bf16.f32 "
        "{%0,%1,%2,%3}, {%4,%5,%6,%7}, {%8,%9}, {%0,%1,%2,%3};"
        : "+f"(c[0]), "+f"(c[1]), "+f"(c[2]), "+f"(c[3])
        : "r"(a[0]), "r"(a[1]), "r"(a[2]), "r"(a[3]), "r"(b0), "r"(b1));
}

// ======================= conversion kernels =======================
__global__ void __launch_bounds__(256)
k_conv_wte(const float* __restrict__ src)
{
    size_t i = ((size_t)blockIdx.x * 256 + threadIdx.x) * 4;
    float4 v = *reinterpret_cast<const float4*>(src + i);
    ushort4 H, L;
#pragma unroll
    for (int q = 0; q < 4; q++) {
        float x = (&v.x)[q];
        __nv_bfloat16 h = __float2bfloat16(x);
        (&H.x)[q] = __bfloat16_as_ushort(h);
        (&L.x)[q] = __bfloat16_as_ushort(__float2bfloat16(x - __bfloat162float(h)));
    }
    *reinterpret_cast<ushort4*>(g_wte_hi + i) = H;
    *reinterpret_cast<ushort4*>(g_wte_lo + i) = L;
}

__global__ void __launch_bounds__(256)
k_conv_w(const float* __restrict__ W, int g)
{
    int idx = blockIdx.x * 256 + threadIdx.x;     // dest n*512 + k
    int n = idx >> 9, k = idx & 511;
    float x = W[k * 256 + n];
    __nv_bfloat16 h = __float2bfloat16(x);
    g_wt_hi[(size_t)g * 131072 + idx] = h;
    g_wt_lo[(size_t)g * 131072 + idx] = __float2bfloat16(x - __bfloat162float(h));
}

// ======================= mma.sync leaf GEMM =======================
// Block: 128 rows x 128 cols, 8 warps each m32 x n64. grid (256 row-tiles, 6 col-tiles).
// K=512 staged in 8 chunks of 64; smem rows pitched 144B (ldmatrix conflict-free).
#define LPITCH 144
#define SA_H 0
#define SA_L 18432
#define SB_H 36864
#define SB_L 55296
#define LEAF_SMEM 73728

__global__ void k_leaf_mma()
{
    extern __shared__ char sm[];
    const int tid = threadIdx.x;
    const int rt = blockIdx.x;
    const int ny = blockIdx.y;
    const int lane = tid & 31;
    const int wid = tid >> 5;
    const int wm = (wid & 3) * 32;       // warp row offset
    const int wn = (wid >> 2) * 64;      // warp col offset

    // staging pointers (per thread: one half-row of 32 bf16 per array)
    const int r = tid >> 1, half = tid & 1;
    const int R = rt * 128 + r;
    const int node = 255 + (R >> 7);
    const int b = R & 127;
    const __nv_bfloat16* arh = g_wte_hi + (size_t)(b * NNODES + node) * INDIM;
    const __nv_bfloat16* arl = g_wte_lo + (size_t)(b * NNODES + node) * INDIM;
    const __nv_bfloat16* brh = g_wt_hi + (size_t)(ny * 128 + r) * 512;
    const __nv_bfloat16* brl = g_wt_lo + (size_t)(ny * 128 + r) * 512;
    char* dAh = sm + SA_H + r * LPITCH + half * 64;
    char* dAl = sm + SA_L + r * LPITCH + half * 64;
    char* dBh = sm + SB_H + r * LPITCH + half * 64;
    char* dBl = sm + SB_L + r * LPITCH + half * 64;

    const uint32_t sbase = smem_u32(sm);
    // fragment load base addresses
    const uint32_t aAddrH = sbase + SA_H + (uint32_t)(wm + (lane & 15)) * LPITCH + (lane >> 4) * 16;
    const uint32_t aAddrL = sbase + SA_L + (uint32_t)(wm + (lane & 15)) * LPITCH + (lane >> 4) * 16;
    const uint32_t bAddrH = sbase + SB_H + (uint32_t)(wn + (lane & 15)) * LPITCH + (lane >> 4) * 16;
    const uint32_t bAddrL = sbase + SB_L + (uint32_t)(wn + (lane & 15)) * LPITCH + (lane >> 4) * 16;

    float c[2][8][4];
#pragma unroll
    for (int mt = 0; mt < 2; mt++)
#pragma unroll
        for (int j = 0; j < 8; j++)
#pragma unroll
            for (int q = 0; q < 4; q++) c[mt][j][q] = 0.0f;

    for (int kc = 0; kc < 8; kc++) {
        const int k0 = kc * 64 + half * 32;   // element offset
        // stage chunk
#pragma unroll
        for (int i = 0; i < 4; i++) {
            *reinterpret_cast<float4*>(dAh + i * 16) =
                *reinterpret_cast<const float4*>(reinterpret_cast<const char*>(arh + k0) + i * 16);
            *reinterpret_cast<float4*>(dAl + i * 16) =
                *reinterpret_cast<const float4*>(reinterpret_cast<const char*>(arl + k0) + i * 16);
            *reinterpret_cast<float4*>(dBh + i * 16) =
                *reinterpret_cast<const float4*>(reinterpret_cast<const char*>(brh + k0) + i * 16);
            *reinterpret_cast<float4*>(dBl + i * 16) =
                *reinterpret_cast<const float4*>(reinterpret_cast<const char*>(brl + k0) + i * 16);
        }
        __syncthreads();

#pragma unroll
        for (int ks = 0; ks < 4; ks++) {
            const uint32_t kb = ks * 32;   // byte offset of k16 within chunk
            // B fragments: 4 x ldmatrix.x4 each covering n16 (two n8 frags)
            uint32_t bh[8][2], bl[8][2];
#pragma unroll
            for (int p = 0; p < 4; p++) {
                uint32_t t[4];
                ldm4(t, bAddrH + (uint32_t)p * 16 * LPITCH + kb);
                bh[p * 2][0] = t[0]; bh[p * 2][1] = t[2];
                bh[p * 2 + 1][0] = t[1]; bh[p * 2 + 1][1] = t[3];
                ldm4(t, bAddrL + (uint32_t)p * 16 * LPITCH + kb);
                bl[p * 2][0] = t[0]; bl[p * 2][1] = t[2];
                bl[p * 2 + 1][0] = t[1]; bl[p * 2 + 1][1] = t[3];
            }
#pragma unroll
            for (int mt = 0; mt < 2; mt++) {
                uint32_t ah[4], al[4];
                ldm4(ah, aAddrH + (uint32_t)mt * 16 * LPITCH + kb);
                ldm4(al, aAddrL + (uint32_t)mt * 16 * LPITCH + kb);
#pragma unroll
                for (int j = 0; j < 8; j++) {
                    mma_bf16(c[mt][j], ah, bh[j][0], bh[j][1]);
                    mma_bf16(c[mt][j], ah, bl[j][0], bl[j][1]);
                    mma_bf16(c[mt][j], al, bh[j][0], bh[j][1]);
                }
            }
        }
        __syncthreads();
    }

    // epilogue: c[mt][j] is m16n8: lane row = lane>>2 (+8), col = (lane&3)*2 (+1)
#pragma unroll
    for (int mt = 0; mt < 2; mt++) {
#pragma unroll
        for (int j = 0; j < 8; j++) {
            int row = rt * 128 + wm + mt * 16 + (lane >> 2);
            int nn = ny * 128 + wn + j * 8 + (lane & 3) * 2;
            int gate = nn >> 8;
            int m = nn & 255;
            float* dst = g_pre + (size_t)gate * 8388608ull + (size_t)row * 256 + m;
            *reinterpret_cast<float2*>(dst) = make_float2(c[mt][j][0], c[mt][j][1]);
            *reinterpret_cast<float2*>(dst + 8 * 256) = make_float2(c[mt][j][2], c[mt][j][3]);
        }
    }
}

__global__ void __launch_bounds__(256)
k_leaf_combine(const float* __restrict__ bix, const float* __restrict__ bih,
               const float* __restrict__ bux, const float* __restrict__ buh,
               const float* __restrict__ boxb, const float* __restrict__ boh)
{
    int idx = blockIdx.x * 256 + threadIdx.x;
    int lin = idx * 4;
    int R = lin >> 8;
    int m = lin & 255;
    size_t off = (size_t)R * 256 + m;
    float4 vi = *reinterpret_cast<const float4*>(g_pre + off);
    float4 vu = *reinterpret_cast<const float4*>(g_pre + 8388608ull + off);
    float4 vo = *reinterpret_cast<const float4*>(g_pre + 16777216ull + off);
    int node = 255 + (R >> 7);
    int b = R & 127;
    size_t base = (size_t)(node * BATCH + b) * MDIM + m;
    float4 cv, hv;
#pragma unroll
    for (int q = 0; q < 4; q++) {
        float iv = sigf((&vi.x)[q] + bix[m + q] + bih[m + q]);
        float uv = tanhf((&vu.x)[q] + bux[m + q] + buh[m + q]);
        float ov = sigf((&vo.x)[q] + boxb[m + q] + boh[m + q]);
        float c = iv * uv;
        (&cv.x)[q] = c;
        (&hv.x)[q] = ov * tanhf(c);
    }
    *reinterpret_cast<float4*>(&g_c_buf[base]) = cv;
    *reinterpret_cast<float4*>(&g_h_buf[base]) = hv;
}

// ======================= R3 FFMA GEMM (cells + gates) =======================
template<int NACC>
__device__ __forceinline__ void gemm_phase(
    ull (*acc)[4][2],
    const float* const* rowptr,
    const float* const (&Bp)[NACC],
    int ldb, int K,
    float* sA, float* sB, int tid)
{
    const int ty = tid >> 4, tx = tid & 15;
    const int ar = tid >> 2, akv = (tid & 3) * 4;
    const int bk = tid >> 4, bnv = (tid & 15) * 4;
    const float* aptr = rowptr[ar];
    const int ASZ = BK * SAS;
    const int BSZ = NACC * BK * BN;

    float4 av = *reinterpret_cast<const float4*>(aptr + akv);
    float4 bv[NACC];
#pragma unroll
    for (int j = 0; j < NACC; j++)
        bv[j] = *reinterpret_cast<const float4*>(Bp[j] + (size_t)bk * ldb + bnv);

    sA[(akv + 0) * SAS + ar] = av.x;
    sA[(akv + 1) * SAS + ar] = av.y;
    sA[(akv + 2) * SAS + ar] = av.z;
    sA[(akv + 3) * SAS + ar] = av.w;
#pragma unroll
    for (int j = 0; j < NACC; j++)
        *reinterpret_cast<float4*>(&sB[(j * BK + bk) * BN + bnv]) = bv[j];
    __syncthreads();

    int cur = 0;
    for (int k0 = 0; k0 < K; k0 += BK) {
        const bool more = (k0 + BK) < K;
        if (more) {
            av = *reinterpret_cast<const float4*>(aptr + k0 + BK + akv);
#pragma unroll
            for (int j = 0; j < NACC; j++)
                bv[j] = *reinterpret_cast<const float4*>(Bp[j] + (size_t)(k0 + BK + bk) * ldb + bnv);
        }
        const float* cA = sA + cur * ASZ;
        const float* cB = sB + cur * BSZ;
#pragma unroll
        for (int kk = 0; kk < BK; kk++) {
            float2 alo2 = *reinterpret_cast<const float2*>(cA + kk * SAS + ty * 4);
            float2 ahi2 = *reinterpret_cast<const float2*>(cA + kk * SAS + ty * 4 + 2);
            ull a0 = pack2(alo2.x);
            ull a1 = pack2(alo2.y);
            ull a2 = pack2(ahi2.x);
            ull a3 = pack2(ahi2.y);
#pragma unroll
            for (int j = 0; j < NACC; j++) {
                ulonglong2 b = *reinterpret_cast<const ulonglong2*>(cB + (j * BK + kk) * BN + tx * 4);
                ffma2(acc[j][0][0], a0, b.x); ffma2(acc[j][0][1], a0, b.y);
                ffma2(acc[j][1][0], a1, b.x); ffma2(acc[j][1][1], a1, b.y);
                ffma2(acc[j][2][0], a2, b.x); ffma2(acc[j][2][1], a2, b.y);
                ffma2(acc[j][3][0], a3, b.x); ffma2(acc[j][3][1], a3, b.y);
            }
        }
        if (more) {
            const int nxt = cur ^ 1;
            float* nA = sA + nxt * ASZ;
            float* nB = sB + nxt * BSZ;
            nA[(akv + 0) * SAS + ar] = av.x;
            nA[(akv + 1) * SAS + ar] = av.y;
            nA[(akv + 2) * SAS + ar] = av.z;
            nA[(akv + 3) * SAS + ar] = av.w;
#pragma unroll
            for (int j = 0; j < NACC; j++)
                *reinterpret_cast<float4*>(&nB[(j * BK + bk) * BN + bnv]) = bv[j];
            __syncthreads();
            cur = nxt;
        }
    }
}

__global__ void __launch_bounds__(NTH, 2)
k_cell1(const float* __restrict__ rel,
        const float* __restrict__ Wsih,
        const float* __restrict__ bsi, const float* __restrict__ bsh,
        int nodeBase)
{
    __shared__ __align__(16) float sA[2 * BK * SAS];
    __shared__ __align__(16) float sB[2 * 3 * BK * BN];
    __shared__ const float* rowptr[BM];
    const int tid = threadIdx.x;
    const int rb = blockIdx.x * BM;
    const int n0 = blockIdx.y * BN;

    ull acc[3][4][2];
#pragma unroll
    for (int j = 0; j < 3; j++)
#pragma unroll
        for (int i = 0; i < 4; i++) { acc[j][i][0] = 0ull; acc[j][i][1] = 0ull; }

    if (tid < BM) {
        int r = rb + tid;
        int node = nodeBase + (r >> 7);
        int b = r & 127;
        rowptr[tid] = g_h_buf + (size_t)((2 * node + 1) * BATCH + b) * MDIM;
    }
    __syncthreads();
    {
        const float* const Bp[3] = { Wsih + n0, Wsih + 512 + n0, Wsih + 768 + n0 };
        gemm_phase<3>(acc, rowptr, Bp, 1024, MDIM, sA, sB, tid);
    }
    __syncthreads();
    if (tid < BM) {
        int r = rb + tid;
        int node = nodeBase + (r >> 7);
        int b = r & 127;
        rowptr[tid] = rel + (size_t)(b * NNODES + 2 * node + 1) * RDIM;
    }
    __syncthreads();
    {
        const float* const Bp[3] = { Wsih + 256 * 1024 + n0, Wsih + 256 * 1024 + 512 + n0,
                                     Wsih + 256 * 1024 + 768 + n0 };
        gemm_phase<3>(acc, rowptr, Bp, 1024, RDIM, sA, sB, tid);
    }
    const int ty = tid >> 4, tx = tid & 15;
    const int m0 = n0 + tx * 4;
#pragma unroll
    for (int i = 0; i < 4; i++) {
        int r = rb + ty * 4 + i;
        size_t base = (size_t)r * MDIM + m0;
        float A[3][4];
#pragma unroll
        for (int j = 0; j < 3; j++) {
            unp2(acc[j][i][0], A[j][0], A[j][1]);
            unp2(acc[j][i][1], A[j][2], A[j][3]);
        }
        float4 hv, cv;
        float* hp = (float*)&hv; float* cp = (float*)&cv;
#pragma unroll
        for (int q = 0; q < 4; q++) {
            int m = m0 + q;
            float iv = sigf(A[0][q] + bsi[m] + bsh[m]);
            float gv = tanhf(A[1][q] + bsi[512 + m] + bsh[512 + m]);
            float ov = sigf(A[2][q] + bsi[768 + m] + bsh[768 + m]);
            float c1 = iv * gv;
            cp[q] = c1;
            hp[q] = ov * tanhf(c1);
        }
        *reinterpret_cast<float4*>(&g_h1[base]) = hv;
        *reinterpret_cast<float4*>(&g_c1[base]) = cv;
    }
}

__global__ void __launch_bounds__(NTH, 2)
k_cell2(const float* __restrict__ rel,
        const float* __restrict__ Wsih, const float* __restrict__ Wshh,
        const float* __restrict__ bsi, const float* __restrict__ bsh,
        int nodeBase)
{
    __shared__ __align__(16) float sA[2 * BK * SAS];
    __shared__ __align__(16) float sB[2 * 4 * BK * BN];
    __shared__ const float* rowptr[BM];
    const int tid = threadIdx.x;
    const int rb = blockIdx.x * BM;
    const int n0 = blockIdx.y * BN;

    ull acc[4][4][2];
#pragma unroll
    for (int j = 0; j < 4; j++)
#pragma unroll
        for (int i = 0; i < 4; i++) { acc[j][i][0] = 0ull; acc[j][i][1] = 0ull; }

    if (tid < BM) {
        int r = rb + tid;
        int node = nodeBase + (r >> 7);
        int b = r & 127;
        rowptr[tid] = g_h_buf + (size_t)((2 * node + 2) * BATCH + b) * MDIM;
    }
    __syncthreads();
    {
        const float* const Bp[4] = { Wsih + n0, Wsih + 256 + n0, Wsih + 512 + n0, Wsih + 768 + n0 };
        gemm_phase<4>(acc, rowptr, Bp, 1024, MDIM, sA, sB, tid);
    }
    __syncthreads();
    if (tid < BM) {
        int r = rb + tid;
        int node = nodeBase + (r >> 7);
        int b = r & 127;
        rowptr[tid] = rel + (size_t)(b * NNODES + 2 * node + 2) * RDIM;
    }
    __syncthreads();
    {
        const float* const Bp[4] = { Wsih + 256 * 1024 + n0, Wsih + 256 * 1024 + 256 + n0,
                                     Wsih + 256 * 1024 + 512 + n0, Wsih + 256 * 1024 + 768 + n0 };
        gemm_phase<4>(acc, rowptr, Bp, 1024, RDIM, sA, sB, tid);
    }
    __syncthreads();
    if (tid < BM) {
        int r = rb + tid;
        rowptr[tid] = g_h1 + (size_t)r * MDIM;
    }
    __syncthreads();
    {
        const float* const Bp[4] = { Wshh + n0, Wshh + 256 + n0, Wshh + 512 + n0, Wshh + 768 + n0 };
        gemm_phase<4>(acc, rowptr, Bp, 1024, MDIM, sA, sB, tid);
    }
    const int ty = tid >> 4, tx = tid & 15;
    const int m0 = n0 + tx * 4;
#pragma unroll
    for (int i = 0; i < 4; i++) {
        int r = rb + ty * 4 + i;
        size_t base = (size_t)r * MDIM + m0;
        float A[4][4];
#pragma unroll
        for (int j = 0; j < 4; j++) {
            unp2(acc[j][i][0], A[j][0], A[j][1]);
            unp2(acc[j][i][1], A[j][2], A[j][3]);
        }
        float4 c1v = *reinterpret_cast<const float4*>(&g_c1[base]);
        const float* c1p = (const float*)&c1v;
        float4 hv;
        float* hp = (float*)&hv;
#pragma unroll
        for (int q = 0; q < 4; q++) {
            int m = m0 + q;
            float iv = sigf(A[0][q] + bsi[m] + bsh[m]);
            float fv = sigf(A[1][q] + bsi[256 + m] + bsh[256 + m]);
            float gv = tanhf(A[2][q] + bsi[512 + m] + bsh[512 + m]);
            float ov = sigf(A[3][q] + bsi[768 + m] + bsh[768 + m]);
            float c2 = fv * c1p[q] + iv * gv;
            hp[q] = ov * tanhf(c2);
        }
        *reinterpret_cast<float4*>(&g_ht[base]) = hv;
    }
}

__global__ void __launch_bounds__(NTH, 2)
k_gates(const float* __restrict__ wte,
        const float* __restrict__ Wix, const float* __restrict__ Wux,
        const float* __restrict__ Wox, const float* __restrict__ Wfx,
        const float* __restrict__ Wih, const float* __restrict__ Wuh,
        const float* __restrict__ Woh, const float* __restrict__ Wfh,
        const float* __restrict__ bix, const float* __restrict__ bux,
        const float* __restrict__ boxb, const float* __restrict__ bfx,
        const float* __restrict__ bih, const float* __restrict__ buh,
        const float* __restrict__ boh, const float* __restrict__ bfh,
        int nodeBase, float* __restrict__ outp)
{
    __shared__ __align__(16) float sA[2 * BK * SAS];
    __shared__ __align__(16) float sB[2 * 4 * BK * BN];
    __shared__ const float* rowptr[BM];
    const int tid = threadIdx.x;
    const int rb = blockIdx.x * BM;
    const int n0 = blockIdx.y * BN;

    ull acc[4][4][2];
    ull accF0[1][4][2], accF1[1][4][2];
#pragma unroll
    for (int j = 0; j < 4; j++)
#pragma unroll
        for (int i = 0; i < 4; i++) { acc[j][i][0] = 0ull; acc[j][i][1] = 0ull; }
#pragma unroll
    for (int i = 0; i < 4; i++) {
        accF0[0][i][0] = 0ull; accF0[0][i][1] = 0ull;
        accF1[0][i][0] = 0ull; accF1[0][i][1] = 0ull;
    }

    if (tid < BM) {
        int r = rb + tid;
        int node = nodeBase + (r >> 7);
        int b = r & 127;
        rowptr[tid] = wte + (size_t)(b * NNODES + node) * INDIM;
    }
    __syncthreads();
    {
        const float* const Bp[4] = { Wix + n0, Wux + n0, Wox + n0, Wfx + n0 };
        gemm_phase<4>(acc, rowptr, Bp, MDIM, INDIM, sA, sB, tid);
    }
    __syncthreads();
    if (tid < BM) {
        int r = rb + tid;
        rowptr[tid] = g_ht + (size_t)r * MDIM;
    }
    __syncthreads();
    {
        const float* const Bp[3] = { Wih + n0, Wuh + n0, Woh + n0 };
        gemm_phase<3>(acc, rowptr, Bp, MDIM, MDIM, sA, sB, tid);
    }
    __syncthreads();
    if (tid < BM) {
        int r = rb + tid;
        int node = nodeBase + (r >> 7);
        int b = r & 127;
        rowptr[tid] = g_h_buf + (size_t)((2 * node + 1) * BATCH + b) * MDIM;
    }
    __syncthreads();
    {
        const float* const Bp[1] = { Wfh + n0 };
        gemm_phase<1>(accF0, rowptr, Bp, MDIM, MDIM, sA, sB, tid);
    }
    __syncthreads();
    if (tid < BM) {
        int r = rb + tid;
        int node = nodeBase + (r >> 7);
        int b = r & 127;
        rowptr[tid] = g_h_buf + (size_t)((2 * node + 2) * BATCH + b) * MDIM;
    }
    __syncthreads();
    {
        const float* const Bp[1] = { Wfh + n0 };
        gemm_phase<1>(accF1, rowptr, Bp, MDIM, MDIM, sA, sB, tid);
    }

    const int ty = tid >> 4, tx = tid & 15;
    const int m0 = n0 + tx * 4;
#pragma unroll
    for (int i = 0; i < 4; i++) {
        int r = rb + ty * 4 + i;
        int node = nodeBase + (r >> 7);
        int b = r & 127;
        int c0n = 2 * node + 1;
        int c1n = 2 * node + 2;
        size_t base  = (size_t)(node * BATCH + b) * MDIM + m0;
        size_t base0 = (size_t)(c0n * BATCH + b) * MDIM + m0;
        size_t base1 = (size_t)(c1n * BATCH + b) * MDIM + m0;
        float A[4][4], F0[4], F1[4];
#pragma unroll
        for (int j = 0; j < 4; j++) {
            unp2(acc[j][i][0], A[j][0], A[j][1]);
            unp2(acc[j][i][1], A[j][2], A[j][3]);
        }
        unp2(accF0[0][i][0], F0[0], F0[1]);
        unp2(accF0[0][i][1], F0[2], F0[3]);
        unp2(accF1[0][i][0], F1[0], F1[1]);
        unp2(accF1[0][i][1], F1[2], F1[3]);
        float4 cc0 = *reinterpret_cast<const float4*>(&g_c_buf[base0]);
        float4 cc1 = *reinterpret_cast<const float4*>(&g_c_buf[base1]);
        const float* cc0p = (const float*)&cc0;
        const float* cc1p = (const float*)&cc1;
        float4 hv, cv;
        float* hp = (float*)&hv; float* cp = (float*)&cv;
#pragma unroll
        for (int q = 0; q < 4; q++) {
            int m = m0 + q;
            float iv = sigf(A[0][q] + bix[m] + bih[m]);
            float uv = tanhf(A[1][q] + bux[m] + buh[m]);
            float ov = sigf(A[2][q] + boxb[m] + boh[m]);
            float fx = A[3][q] + bfx[m] + bfh[m];
            float f0 = sigf(fx + F0[q]);
            float f1 = sigf(fx + F1[q]);
            float c = iv * uv + f0 * cc0p[q] + f1 * cc1p[q];
            cp[q] = c;
            hp[q] = ov * tanhf(c);
        }
        *reinterpret_cast<float4*>(&g_h_buf[base]) = hv;
        *reinterpret_cast<float4*>(&g_c_buf[base]) = cv;
        if (outp) {
            *reinterpret_cast<float4*>(&outp[(size_t)r * MDIM + m0]) = hv;
        }
    }
}

extern "C" void kernel_launch(void* const* d_in, const int* in_sizes, int n_in,
                              void* d_out, int out_size)
{
    const float* wte = nullptr;
    const float* rel = nullptr;
    const float* Wx[4];  int nWx = 0;
    const float* Wh[4];  int nWh = 0;
    const float* b256[8]; int nb = 0;
    const float* Wsih = nullptr;
    const float* Wshh = nullptr;
    const float* bseq[2]; int nbs = 0;

    for (int i = 0; i < n_in; i++) {
        int s = in_sizes[i];
        const float* p = (const float*)d_in[i];
        switch (s) {
            case 33488896: wte = p; break;
            case 4186112:  rel = p; break;
            case 131072:   if (nWx < 4) Wx[nWx++] = p; break;
            case 65536:    if (nWh < 4) Wh[nWh++] = p; break;
            case 256:      if (nb < 8) b256[nb++] = p; break;
            case 327680:   Wsih = p; break;
            case 262144:   Wshh = p; break;
            case 1024:     if (nbs < 2) bseq[nbs++] = p; break;
            default: break;
        }
    }
    const float *Wix = Wx[0], *Wfx = Wx[1], *Wux = Wx[2], *Wox = Wx[3];
    const float *Wih = Wh[0], *Wfh = Wh[1], *Wuh = Wh[2], *Woh = Wh[3];
    const float *bix = b256[0], *bfx = b256[1], *bux = b256[2], *boxb = b256[3];
    const float *bih = b256[4], *bfh = b256[5], *buh = b256[6], *boh = b256[7];
    float* out = (float*)d_out;

    cudaFuncSetAttribute(k_leaf_mma, cudaFuncAttributeMaxDynamicSharedMemorySize, LEAF_SMEM);

    dim3 blk(NTH);

    // --- Leaf via mma.sync bf16-split ---
    k_conv_wte<<<32704, 256>>>(wte);
    k_conv_w<<<512, 256>>>(Wix, 0);
    k_conv_w<<<512, 256>>>(Wux, 1);
    k_conv_w<<<512, 256>>>(Wox, 2);
    k_leaf_mma<<<dim3(256, 6), 256, LEAF_SMEM>>>();
    k_leaf_combine<<<8192, 256>>>(bix, bih, bux, buh, boxb, boh);

    // --- Levels 7..0 (R3 FFMA path) ---
    for (int L = 7; L >= 0; --L) {
        int P = 1 << L;
        int nodeBase = P - 1;
        int rowBlocks = (P * BATCH) / BM;
        dim3 grd(rowBlocks, 4);
        k_cell1<<<grd, blk>>>(rel, Wsih, bseq[0], bseq[1], nodeBase);
        k_cell2<<<grd, blk>>>(rel, Wsih, Wshh, bseq[0], bseq[1], nodeBase);
        k_gates<<<grd, blk>>>(wte, Wix, Wux, Wox, Wfx, Wih, Wuh, Woh, Wfh,
                              bix, bux, boxb, bfx, bih, buh, boh, bfh,
                              nodeBase, (L == 0) ? out : nullptr);
    }
}

// round 11
// speedup vs baseline: 2.1217x; 1.3763x over previous
#include <cuda_runtime.h>
#include <cuda_bf16.h>
#include <cstdint>
#include <cstddef>
#include <math.h>

// Problem constants (B=128, N=511, M=256, R=64, IN=512)
#define BATCH  128
#define NNODES 511
#define MDIM   256
#define RDIM   64
#define INDIM  512

typedef unsigned long long ull;

// ---------------- persistent device scratch (no allocation) ----------------
__device__ __align__(16) float g_c_buf[(size_t)NNODES * BATCH * MDIM];
__device__ __align__(16) float g_c1[(size_t)128 * BATCH * MDIM];

// bf16 split activations
__device__ __align__(16) __nv_bfloat16 g_wte_hi[(size_t)BATCH * NNODES * INDIM];
__device__ __align__(16) __nv_bfloat16 g_wte_lo[(size_t)BATCH * NNODES * INDIM];
__device__ __align__(16) __nv_bfloat16 g_relb_hi[(size_t)BATCH * NNODES * RDIM];
__device__ __align__(16) __nv_bfloat16 g_relb_lo[(size_t)BATCH * NNODES * RDIM];
__device__ __align__(16) __nv_bfloat16 g_hb_hi[(size_t)NNODES * BATCH * MDIM];
__device__ __align__(16) __nv_bfloat16 g_hb_lo[(size_t)NNODES * BATCH * MDIM];
__device__ __align__(16) __nv_bfloat16 g_h1b_hi[(size_t)128 * BATCH * MDIM];
__device__ __align__(16) __nv_bfloat16 g_h1b_lo[(size_t)128 * BATCH * MDIM];
__device__ __align__(16) __nv_bfloat16 g_htb_hi[(size_t)128 * BATCH * MDIM];
__device__ __align__(16) __nv_bfloat16 g_htb_lo[(size_t)128 * BATCH * MDIM];

// bf16 split weights (transposed [N][K])
__device__ __align__(16) __nv_bfloat16 g_wt_hi[768 * 512];     // leaf (i,u,o)
__device__ __align__(16) __nv_bfloat16 g_wt_lo[768 * 512];
__device__ __align__(16) __nv_bfloat16 g_wc1_hi[768 * 320];
__device__ __align__(16) __nv_bfloat16 g_wc1_lo[768 * 320];
__device__ __align__(16) __nv_bfloat16 g_wc2_hi[1024 * 576];
__device__ __align__(16) __nv_bfloat16 g_wc2_lo[1024 * 576];
__device__ __align__(16) __nv_bfloat16 g_wg_hi[1024 * 768];
__device__ __align__(16) __nv_bfloat16 g_wg_lo[1024 * 768];
__device__ __align__(16) __nv_bfloat16 g_wfh_hi[256 * 256];
__device__ __align__(16) __nv_bfloat16 g_wfh_lo[256 * 256];

// pre-activation scratch
__device__ __align__(16) float g_prel[(size_t)32768 * 768];
__device__ __align__(16) float g_pre1[(size_t)16384 * 768];
__device__ __align__(16) float g_pre2[(size_t)16384 * 1024];
__device__ __align__(16) float g_preg[(size_t)16384 * 1024];
__device__ __align__(16) float g_pref[(size_t)32768 * 256];

__device__ __forceinline__ float sigf(float x) { return 1.0f / (1.0f + expf(-x)); }

__device__ __forceinline__ void split2(float x, unsigned short& h, unsigned short& l) {
    __nv_bfloat16 bh = __float2bfloat16(x);
    h = __bfloat16_as_ushort(bh);
    l = __bfloat16_as_ushort(__float2bfloat16(x - __bfloat162float(bh)));
}

// ---- mma.sync helpers ----
__device__ __forceinline__ uint32_t smem_u32(const void* p) {
    uint32_t a;
    asm("{ .reg .u64 t; cvta.to.shared.u64 t, %1; cvt.u32.u64 %0, t; }" : "=r"(a) : "l"(p));
    return a;
}
__device__ __forceinline__ void ldm4(uint32_t* r, uint32_t addr) {
    asm volatile("ldmatrix.sync.aligned.m8n8.x4.shared.b16 {%0,%1,%2,%3}, [%4];"
        : "=r"(r[0]), "=r"(r[1]), "=r"(r[2]), "=r"(r[3]) : "r"(addr));
}
__device__ __forceinline__ void mma_bf16(float* c, const uint32_t* a,
                                         uint32_t b0, uint32_t b1) {
    asm volatile(
        "mma.sync.aligned.m16n8k16.row.col.f32.bf16.bf16.f32 "
        "{%0,%1,%2,%3}, {%4,%5,%6,%7}, {%8,%9}, {%0,%1,%2,%3};"
        : "+f"(c[0]), "+f"(c[1]), "+f"(c[2]), "+f"(c[3])
        : "r"(a[0]), "r"(a[1]), "r"(a[2]), "r"(a[3]), "r"(b0), "r"(b1));
}
#define CPA16(s, g) asm volatile("cp.async.cg.shared.global [%0], [%1], 16;" :: "r"(s), "l"(g))
#define CPC() asm volatile("cp.async.commit_group;" ::: "memory")
#define CPW(n) asm volatile("cp.async.wait_group %0;" :: "n"(n) : "memory")

// ======================= conversion kernels =======================
__global__ void __launch_bounds__(256)
k_conv_wte(const float* __restrict__ src)
{
    size_t i = ((size_t)blockIdx.x * 256 + threadIdx.x) * 4;
    float4 v = *reinterpret_cast<const float4*>(src + i);
    ushort4 H, L;
#pragma unroll
    for (int q = 0; q < 4; q++) split2((&v.x)[q], (&H.x)[q], (&L.x)[q]);
    *reinterpret_cast<ushort4*>(g_wte_hi + i) = H;
    *reinterpret_cast<ushort4*>(g_wte_lo + i) = L;
}

__global__ void __launch_bounds__(256)
k_conv_rel(const float* __restrict__ src)
{
    size_t i = ((size_t)blockIdx.x * 256 + threadIdx.x) * 4;
    float4 v = *reinterpret_cast<const float4*>(src + i);
    ushort4 H, L;
#pragma unroll
    for (int q = 0; q < 4; q++) split2((&v.x)[q], (&H.x)[q], (&L.x)[q]);
    *reinterpret_cast<ushort4*>(g_relb_hi + i) = H;
    *reinterpret_cast<ushort4*>(g_relb_lo + i) = L;
}

__global__ void __launch_bounds__(256)
k_conv_w(const float* __restrict__ W, int g)   // leaf weights -> [768][512]
{
    int idx = blockIdx.x * 256 + threadIdx.x;
    int n = idx >> 9, k = idx & 511;
    float x = W[k * 256 + n];
    unsigned short h, l;
    split2(x, h, l);
    g_wt_hi[(size_t)g * 131072 + idx] = __ushort_as_bfloat16(h);
    g_wt_lo[(size_t)g * 131072 + idx] = __ushort_as_bfloat16(l);
}

__global__ void __launch_bounds__(256)
k_conv_c1(const float* __restrict__ Wsih)   // [768][320]
{
    int idx = blockIdx.x * 256 + threadIdx.x;
    int n = idx / 320, k = idx % 320;
    int m = n & 255, gsel = n >> 8;
    int cbase = (gsel == 0) ? 0 : (gsel == 1 ? 512 : 768);   // i, g, o
    float x = Wsih[(size_t)k * 1024 + cbase + m];
    unsigned short h, l;
    split2(x, h, l);
    g_wc1_hi[idx] = __ushort_as_bfloat16(h);
    g_wc1_lo[idx] = __ushort_as_bfloat16(l);
}

__global__ void __launch_bounds__(256)
k_conv_c2(const float* __restrict__ Wsih, const float* __restrict__ Wshh)  // [1024][576]
{
    int idx = blockIdx.x * 256 + threadIdx.x;
    int n = idx / 576, k = idx % 576;
    int m = n & 255, cbase = (n >> 8) * 256;   // i, f, g, o
    float x = (k < 320) ? Wsih[(size_t)k * 1024 + cbase + m]
                        : Wshh[(size_t)(k - 320) * 1024 + cbase + m];
    unsigned short h, l;
    split2(x, h, l);
    g_wc2_hi[idx] = __ushort_as_bfloat16(h);
    g_wc2_lo[idx] = __ushort_as_bfloat16(l);
}

__global__ void __launch_bounds__(256)
k_conv_g(const float* __restrict__ Wix, const float* __restrict__ Wux,
         const float* __restrict__ Wox, const float* __restrict__ Wfx,
         const float* __restrict__ Wih, const float* __restrict__ Wuh,
         const float* __restrict__ Woh)    // [1024][768]: gates i,u,o,fx
{
    int idx = blockIdx.x * 256 + threadIdx.x;
    int n = idx / 768, k = idx % 768;
    int m = n & 255, gate = n >> 8;
    float x;
    if (k < 512) {
        const float* W = (gate == 0) ? Wix : (gate == 1) ? Wux : (gate == 2) ? Wox : Wfx;
        x = W[(size_t)k * 256 + m];
    } else if (gate < 3) {
        const float* W = (gate == 0) ? Wih : (gate == 1) ? Wuh : Woh;
        x = W[(size_t)(k - 512) * 256 + m];
    } else {
        x = 0.0f;
    }
    unsigned short h, l;
    split2(x, h, l);
    g_wg_hi[idx] = __ushort_as_bfloat16(h);
    g_wg_lo[idx] = __ushort_as_bfloat16(l);
}

__global__ void __launch_bounds__(256)
k_conv_fh(const float* __restrict__ Wfh)   // [256][256]
{
    int idx = blockIdx.x * 256 + threadIdx.x;
    int n = idx >> 8, k = idx & 255;
    float x = Wfh[(size_t)k * 256 + n];
    unsigned short h, l;
    split2(x, h, l);
    g_wfh_hi[idx] = __ushort_as_bfloat16(h);
    g_wfh_lo[idx] = __ushort_as_bfloat16(l);
}

// ======================= generic bf16-split mma GEMM =======================
// Block 128 rows x 128 cols, 8 warps (m32 x n64). K in 64-chunks, 2-stage cp.async.
// MODE: 0=cell1(5 chunks,K=320) 1=cell2(9,576) 2=gates(12,768) 3=f(4,256) 4=leaf(8,512)
#define LPITCH 144
#define STG 73728

template<int MODE, int NC, int COLS, int KTOT>
__global__ void __launch_bounds__(256, 1)
k_mma(int nodeBase, int P)
{
    extern __shared__ char sm[];
    const int tid = threadIdx.x;
    const int rt = blockIdx.x, ny = blockIdx.y;
    const int lane = tid & 31, wid = tid >> 5;
    const int wm = (wid & 3) * 32, wn = (wid >> 2) * 64;
    const int r = tid >> 1, half = tid & 1;

    // MODE-selected globals (compile-time; fixes the host-passed __device__ ptr bug)
    const __nv_bfloat16* WH;
    const __nv_bfloat16* WL;
    float* pre;
    if (MODE == 0)      { WH = g_wc1_hi; WL = g_wc1_lo; pre = g_pre1; }
    else if (MODE == 1) { WH = g_wc2_hi; WL = g_wc2_lo; pre = g_pre2; }
    else if (MODE == 2) { WH = g_wg_hi;  WL = g_wg_lo;  pre = g_preg; }
    else if (MODE == 3) { WH = g_wfh_hi; WL = g_wfh_lo; pre = g_pref; }
    else                { WH = g_wt_hi;  WL = g_wt_lo;  pre = g_prel; }

    // A segment base pointers (per staged row r)
    const __nv_bfloat16 *pA0h = nullptr, *pA0l = nullptr;
    const __nv_bfloat16 *pA1h = nullptr, *pA1l = nullptr;
    const __nv_bfloat16 *pA2h = nullptr, *pA2l = nullptr;
    if (MODE == 3) {
        int rt2 = (rt < P) ? rt : rt - P;
        int rl = rt2 * 128 + r;
        int node = nodeBase + (rl >> 7);
        int b = rl & 127;
        int ch = (rt < P) ? (2 * node + 1) : (2 * node + 2);
        pA0h = g_hb_hi + ((size_t)ch * BATCH + b) * 256;
        pA0l = g_hb_lo + ((size_t)ch * BATCH + b) * 256;
    } else if (MODE == 4) {
        int R = rt * 128 + r;
        int node = 255 + (R >> 7);
        int b = R & 127;
        pA0h = g_wte_hi + ((size_t)b * NNODES + node) * 512;
        pA0l = g_wte_lo + ((size_t)b * NNODES + node) * 512;
    } else {
        int rl = rt * 128 + r;
        int node = nodeBase + (rl >> 7);
        int b = rl & 127;
        if (MODE == 0) {
            int ch = 2 * node + 1;
            pA0h = g_hb_hi + ((size_t)ch * BATCH + b) * 256;
            pA0l = g_hb_lo + ((size_t)ch * BATCH + b) * 256;
            pA1h = g_relb_hi + ((size_t)b * NNODES + ch) * 64;
            pA1l = g_relb_lo + ((size_t)b * NNODES + ch) * 64;
        } else if (MODE == 1) {
            int ch = 2 * node + 2;
            pA0h = g_hb_hi + ((size_t)ch * BATCH + b) * 256;
            pA0l = g_hb_lo + ((size_t)ch * BATCH + b) * 256;
            pA1h = g_relb_hi + ((size_t)b * NNODES + ch) * 64;
            pA1l = g_relb_lo + ((size_t)b * NNODES + ch) * 64;
            pA2h = g_h1b_hi + (size_t)rl * 256;
            pA2l = g_h1b_lo + (size_t)rl * 256;
        } else {   // MODE 2
            pA0h = g_wte_hi + ((size_t)b * NNODES + node) * 512;
            pA0l = g_wte_lo + ((size_t)b * NNODES + node) * 512;
            pA1h = g_htb_hi + (size_t)rl * 256;
            pA1l = g_htb_lo + (size_t)rl * 256;
        }
    }
    const __nv_bfloat16* pBh = WH + (size_t)(ny * 128 + r) * KTOT;
    const __nv_bfloat16* pBl = WL + (size_t)(ny * 128 + r) * KTOT;

    const uint32_t sbase = smem_u32(sm);

    auto stage = [&](int c, int s) {
        const __nv_bfloat16 *ah, *al;
        if (MODE == 0) {
            if (c < 4) { ah = pA0h + c * 64; al = pA0l + c * 64; }
            else       { ah = pA1h;          al = pA1l; }
        } else if (MODE == 1) {
            if (c < 4)      { ah = pA0h + c * 64; al = pA0l + c * 64; }
            else if (c == 4){ ah = pA1h;          al = pA1l; }
            else            { ah = pA2h + (c - 5) * 64; al = pA2l + (c - 5) * 64; }
        } else if (MODE == 2) {
            if (c < 8) { ah = pA0h + c * 64;       al = pA0l + c * 64; }
            else       { ah = pA1h + (c - 8) * 64; al = pA1l + (c - 8) * 64; }
        } else {
            ah = pA0h + c * 64; al = pA0l + c * 64;
        }
        const char* gah = reinterpret_cast<const char*>(ah + half * 32);
        const char* gal = reinterpret_cast<const char*>(al + half * 32);
        const char* gbh = reinterpret_cast<const char*>(pBh + c * 64 + half * 32);
        const char* gbl = reinterpret_cast<const char*>(pBl + c * 64 + half * 32);
        uint32_t base = sbase + (uint32_t)s * STG + (uint32_t)r * LPITCH + half * 64;
#pragma unroll
        for (int i = 0; i < 4; i++) {
            CPA16(base + 0     + i * 16, gah + i * 16);
            CPA16(base + 18432 + i * 16, gal + i * 16);
            CPA16(base + 36864 + i * 16, gbh + i * 16);
            CPA16(base + 55296 + i * 16, gbl + i * 16);
        }
        CPC();
    };

    float cacc[2][8][4];
#pragma unroll
    for (int mt = 0; mt < 2; mt++)
#pragma unroll
        for (int j = 0; j < 8; j++)
#pragma unroll
            for (int q = 0; q < 4; q++) cacc[mt][j][q] = 0.0f;

    stage(0, 0);
    for (int c = 0; c < NC; c++) {
        if (c + 1 < NC) { stage(c + 1, (c + 1) & 1); CPW(1); }
        else            { CPW(0); }
        __syncthreads();
        const uint32_t sb = sbase + (uint32_t)(c & 1) * STG;
        const uint32_t aH = sb + 0     + (uint32_t)(wm + (lane & 15)) * LPITCH + (lane >> 4) * 16;
        const uint32_t aL = sb + 18432 + (uint32_t)(wm + (lane & 15)) * LPITCH + (lane >> 4) * 16;
        const uint32_t bH = sb + 36864 + (uint32_t)(wn + (lane & 15)) * LPITCH + (lane >> 4) * 16;
        const uint32_t bL = sb + 55296 + (uint32_t)(wn + (lane & 15)) * LPITCH + (lane >> 4) * 16;
#pragma unroll
        for (int ks = 0; ks < 4; ks++) {
            const uint32_t kb = ks * 32;
            uint32_t bh[8][2], bl[8][2];
#pragma unroll
            for (int p = 0; p < 4; p++) {
                uint32_t t[4];
                ldm4(t, bH + (uint32_t)p * 16 * LPITCH + kb);
                bh[p * 2][0] = t[0]; bh[p * 2][1] = t[2];
                bh[p * 2 + 1][0] = t[1]; bh[p * 2 + 1][1] = t[3];
                ldm4(t, bL + (uint32_t)p * 16 * LPITCH + kb);
                bl[p * 2][0] = t[0]; bl[p * 2][1] = t[2];
                bl[p * 2 + 1][0] = t[1]; bl[p * 2 + 1][1] = t[3];
            }
#pragma unroll
            for (int mt = 0; mt < 2; mt++) {
                uint32_t ah[4], al[4];
                ldm4(ah, aH + (uint32_t)mt * 16 * LPITCH + kb);
                ldm4(al, aL + (uint32_t)mt * 16 * LPITCH + kb);
#pragma unroll
                for (int j = 0; j < 8; j++) {
                    mma_bf16(cacc[mt][j], ah, bh[j][0], bh[j][1]);
                    mma_bf16(cacc[mt][j], ah, bl[j][0], bl[j][1]);
                    mma_bf16(cacc[mt][j], al, bh[j][0], bh[j][1]);
                }
            }
        }
        __syncthreads();
    }

    // epilogue: write pre-activations
#pragma unroll
    for (int mt = 0; mt < 2; mt++) {
#pragma unroll
        for (int j = 0; j < 8; j++) {
            int row = rt * 128 + wm + mt * 16 + (lane >> 2);
            int nn = ny * 128 + wn + j * 8 + (lane & 3) * 2;
            float* dst = pre + (size_t)row * COLS + nn;
            *reinterpret_cast<float2*>(dst) = make_float2(cacc[mt][j][0], cacc[mt][j][1]);
            *reinterpret_cast<float2*>(dst + (size_t)8 * COLS) = make_float2(cacc[mt][j][2], cacc[mt][j][3]);
        }
    }
}

// ======================= combine kernels =======================
__global__ void __launch_bounds__(256)
k_comb_leaf(const float* __restrict__ bix, const float* __restrict__ bih,
            const float* __restrict__ bux, const float* __restrict__ buh,
            const float* __restrict__ boxb, const float* __restrict__ boh)
{
    int idx = blockIdx.x * 256 + threadIdx.x;
    int lin = idx * 4;
    int row = lin >> 8, m = lin & 255;
    const float* p = g_prel + (size_t)row * 768;
    float4 vi = *reinterpret_cast<const float4*>(p + m);
    float4 vu = *reinterpret_cast<const float4*>(p + 256 + m);
    float4 vo = *reinterpret_cast<const float4*>(p + 512 + m);
    int node = 255 + (row >> 7);
    int b = row & 127;
    size_t base = ((size_t)node * BATCH + b) * MDIM + m;
    float4 cv;
    ushort4 hh, hl;
#pragma unroll
    for (int q = 0; q < 4; q++) {
        float iv = sigf((&vi.x)[q] + bix[m + q] + bih[m + q]);
        float uv = tanhf((&vu.x)[q] + bux[m + q] + buh[m + q]);
        float ov = sigf((&vo.x)[q] + boxb[m + q] + boh[m + q]);
        float c = iv * uv;
        (&cv.x)[q] = c;
        split2(ov * tanhf(c), (&hh.x)[q], (&hl.x)[q]);
    }
    *reinterpret_cast<float4*>(&g_c_buf[base]) = cv;
    *reinterpret_cast<ushort4*>(g_hb_hi + base) = hh;
    *reinterpret_cast<ushort4*>(g_hb_lo + base) = hl;
}

__global__ void __launch_bounds__(256)
k_comb_c1(const float* __restrict__ bsi, const float* __restrict__ bsh)
{
    int idx = blockIdx.x * 256 + threadIdx.x;
    int lin = idx * 4;
    int row = lin >> 8, m = lin & 255;
    const float* p = g_pre1 + (size_t)row * 768;
    float4 vi = *reinterpret_cast<const float4*>(p + m);
    float4 vg = *reinterpret_cast<const float4*>(p + 256 + m);
    float4 vo = *reinterpret_cast<const float4*>(p + 512 + m);
    size_t base = (size_t)row * MDIM + m;
    float4 cv;
    ushort4 hh, hl;
#pragma unroll
    for (int q = 0; q < 4; q++) {
        float iv = sigf((&vi.x)[q] + bsi[m + q] + bsh[m + q]);
        float gv = tanhf((&vg.x)[q] + bsi[512 + m + q] + bsh[512 + m + q]);
        float ov = sigf((&vo.x)[q] + bsi[768 + m + q] + bsh[768 + m + q]);
        float c1 = iv * gv;
        (&cv.x)[q] = c1;
        split2(ov * tanhf(c1), (&hh.x)[q], (&hl.x)[q]);
    }
    *reinterpret_cast<float4*>(&g_c1[base]) = cv;
    *reinterpret_cast<ushort4*>(g_h1b_hi + base) = hh;
    *reinterpret_cast<ushort4*>(g_h1b_lo + base) = hl;
}

__global__ void __launch_bounds__(256)
k_comb_c2(const float* __restrict__ bsi, const float* __restrict__ bsh)
{
    int idx = blockIdx.x * 256 + threadIdx.x;
    int lin = idx * 4;
    int row = lin >> 8, m = lin & 255;
    const float* p = g_pre2 + (size_t)row * 1024;
    float4 vi = *reinterpret_cast<const float4*>(p + m);
    float4 vf = *reinterpret_cast<const float4*>(p + 256 + m);
    float4 vg = *reinterpret_cast<const float4*>(p + 512 + m);
    float4 vo = *reinterpret_cast<const float4*>(p + 768 + m);
    size_t base = (size_t)row * MDIM + m;
    float4 c1v = *reinterpret_cast<const float4*>(&g_c1[base]);
    ushort4 hh, hl;
#pragma unroll
    for (int q = 0; q < 4; q++) {
        float iv = sigf((&vi.x)[q] + bsi[m + q] + bsh[m + q]);
        float fv = sigf((&vf.x)[q] + bsi[256 + m + q] + bsh[256 + m + q]);
        float gv = tanhf((&vg.x)[q] + bsi[512 + m + q] + bsh[512 + m + q]);
        float ov = sigf((&vo.x)[q] + bsi[768 + m + q] + bsh[768 + m + q]);
        float c2 = fv * (&c1v.x)[q] + iv * gv;
        split2(ov * tanhf(c2), (&hh.x)[q], (&hl.x)[q]);
    }
    *reinterpret_cast<ushort4*>(g_htb_hi + base) = hh;
    *reinterpret_cast<ushort4*>(g_htb_lo + base) = hl;
}

__global__ void __launch_bounds__(256)
k_comb_fin(const float* __restrict__ bix, const float* __restrict__ bih,
           const float* __restrict__ bux, const float* __restrict__ buh,
           const float* __restrict__ boxb, const float* __restrict__ boh,
           const float* __restrict__ bfx, const float* __restrict__ bfh,
           int nodeBase, int P, float* __restrict__ outp)
{
    int idx = blockIdx.x * 256 + threadIdx.x;
    int lin = idx * 4;
    int row = lin >> 8, m = lin & 255;
    const float* p = g_preg + (size_t)row * 1024;
    float4 vi = *reinterpret_cast<const float4*>(p + m);
    float4 vu = *reinterpret_cast<const float4*>(p + 256 + m);
    float4 vo = *reinterpret_cast<const float4*>(p + 512 + m);
    float4 vx = *reinterpret_cast<const float4*>(p + 768 + m);
    float4 f0 = *reinterpret_cast<const float4*>(g_pref + (size_t)row * 256 + m);
    float4 f1 = *reinterpret_cast<const float4*>(g_pref + ((size_t)P * 128 + row) * 256 + m);
    int node = nodeBase + (row >> 7);
    int b = row & 127;
    size_t base  = ((size_t)node * BATCH + b) * MDIM + m;
    size_t base0 = ((size_t)(2 * node + 1) * BATCH + b) * MDIM + m;
    size_t base1 = ((size_t)(2 * node + 2) * BATCH + b) * MDIM + m;
    float4 cc0 = *reinterpret_cast<const float4*>(&g_c_buf[base0]);
    float4 cc1 = *reinterpret_cast<const float4*>(&g_c_buf[base1]);
    float4 cv, hv;
    ushort4 hh, hl;
#pragma unroll
    for (int q = 0; q < 4; q++) {
        float iv = sigf((&vi.x)[q] + bix[m + q] + bih[m + q]);
        float uv = tanhf((&vu.x)[q] + bux[m + q] + buh[m + q]);
        float ov = sigf((&vo.x)[q] + boxb[m + q] + boh[m + q]);
        float fx = (&vx.x)[q] + bfx[m + q] + bfh[m + q];
        float fa = sigf(fx + (&f0.x)[q]);
        float fb = sigf(fx + (&f1.x)[q]);
        float c = iv * uv + fa * (&cc0.x)[q] + fb * (&cc1.x)[q];
        (&cv.x)[q] = c;
        float h = ov * tanhf(c);
        (&hv.x)[q] = h;
        split2(h, (&hh.x)[q], (&hl.x)[q]);
    }
    *reinterpret_cast<float4*>(&g_c_buf[base]) = cv;
    *reinterpret_cast<ushort4*>(g_hb_hi + base) = hh;
    *reinterpret_cast<ushort4*>(g_hb_lo + base) = hl;
    if (outp)
        *reinterpret_cast<float4*>(&outp[(size_t)row * MDIM + m]) = hv;
}

// ======================= launch =======================
extern "C" void kernel_launch(void* const* d_in, const int* in_sizes, int n_in,
                              void* d_out, int out_size)
{
    const float* wte = nullptr;
    const float* rel = nullptr;
    const float* Wx[4];  int nWx = 0;   // ix, fx, ux, ox
    const float* Wh[4];  int nWh = 0;   // ih, fh, uh, oh
    const float* b256[8]; int nb = 0;
    const float* Wsih = nullptr;
    const float* Wshh = nullptr;
    const float* bseq[2]; int nbs = 0;

    for (int i = 0; i < n_in; i++) {
        int s = in_sizes[i];
        const float* p = (const float*)d_in[i];
        switch (s) {
            case 33488896: wte = p; break;
            case 4186112:  rel = p; break;
            case 131072:   if (nWx < 4) Wx[nWx++] = p; break;
            case 65536:    if (nWh < 4) Wh[nWh++] = p; break;
            case 256:      if (nb < 8) b256[nb++] = p; break;
            case 327680:   Wsih = p; break;
            case 262144:   Wshh = p; break;
            case 1024:     if (nbs < 2) bseq[nbs++] = p; break;
            default: break;
        }
    }
    const float *Wix = Wx[0], *Wfx = Wx[1], *Wux = Wx[2], *Wox = Wx[3];
    const float *Wih = Wh[0], *Wfh = Wh[1], *Wuh = Wh[2], *Woh = Wh[3];
    const float *bix = b256[0], *bfx = b256[1], *bux = b256[2], *boxb = b256[3];
    const float *bih = b256[4], *bfh = b256[5], *buh = b256[6], *boh = b256[7];
    float* out = (float*)d_out;

    const int SMSZ = 2 * STG;
    cudaFuncSetAttribute(k_mma<0, 5, 768, 320>,  cudaFuncAttributeMaxDynamicSharedMemorySize, SMSZ);
    cudaFuncSetAttribute(k_mma<1, 9, 1024, 576>, cudaFuncAttributeMaxDynamicSharedMemorySize, SMSZ);
    cudaFuncSetAttribute(k_mma<2, 12, 1024, 768>,cudaFuncAttributeMaxDynamicSharedMemorySize, SMSZ);
    cudaFuncSetAttribute(k_mma<3, 4, 256, 256>,  cudaFuncAttributeMaxDynamicSharedMemorySize, SMSZ);
    cudaFuncSetAttribute(k_mma<4, 8, 768, 512>,  cudaFuncAttributeMaxDynamicSharedMemorySize, SMSZ);

    // conversions
    k_conv_wte<<<32704, 256>>>(wte);
    k_conv_rel<<<4088, 256>>>(rel);
    k_conv_w<<<512, 256>>>(Wix, 0);
    k_conv_w<<<512, 256>>>(Wux, 1);
    k_conv_w<<<512, 256>>>(Wox, 2);
    k_conv_c1<<<960, 256>>>(Wsih);
    k_conv_c2<<<2304, 256>>>(Wsih, Wshh);
    k_conv_g<<<3072, 256>>>(Wix, Wux, Wox, Wfx, Wih, Wuh, Woh);
    k_conv_fh<<<256, 256>>>(Wfh);

    // leaf
    k_mma<4, 8, 768, 512><<<dim3(256, 6), 256, SMSZ>>>(0, 0);
    k_comb_leaf<<<8192, 256>>>(bix, bih, bux, buh, boxb, boh);

    // levels 7..0
    for (int L = 7; L >= 0; --L) {
        int P = 1 << L;
        int nodeBase = P - 1;
        k_mma<0, 5, 768, 320><<<dim3(P, 6), 256, SMSZ>>>(nodeBase, P);
        k_comb_c1<<<P * 32, 256>>>(bseq[0], bseq[1]);
        k_mma<1, 9, 1024, 576><<<dim3(P, 8), 256, SMSZ>>>(nodeBase, P);
        k_comb_c2<<<P * 32, 256>>>(bseq[0], bseq[1]);
        k_mma<2, 12, 1024, 768><<<dim3(P, 8), 256, SMSZ>>>(nodeBase, P);
        k_mma<3, 4, 256, 256><<<dim3(2 * P, 2), 256, SMSZ>>>(nodeBase, P);
        k_comb_fin<<<P * 32, 256>>>(bix, bih, bux, buh, boxb, boh, bfx, bfh,
                                    nodeBase, P, (L == 0) ? out : nullptr);
    }
}